// round 2
// baseline (speedup 1.0000x reference)
#include <cuda_runtime.h>

// LSTM B=2048, T=512, LATENT=18, HID=32 (gates 4H=128), torch gate order i,f,g,o.
//
// Kernel 1 (serial recurrence, the critical path):
//   grid 128 x 128 threads; warp handles 4 batch elements; lane = hidden index.
//   W_hh register-resident as f32x2 pairs (128 regs). W_ih pairs in smem.
//   Pair-accumulation: acc_(gate) holds (even-k partial, odd-k partial); the
//   multiplier (v_2k, v_2k+1) is one broadcast LDS.64; horizontal add at end.
//   h written to global scratch for kernel 2.
// Kernel 2 (parallel, memory-bound): z_pred = h @ W_out^T + b_out.

#define NB 2048
#define NT 512
#define NL 18
#define NH 32
#define NP 9     // latent pairs
#define KP 16    // hidden pairs

typedef unsigned long long u64;

__device__ float g_hscr[(size_t)NB * NT * NH];   // 512 MB scratch: h[B][T][32]

__device__ __forceinline__ u64 pk(float x, float y) {
    u64 r; asm("mov.b64 %0,{%1,%2};" : "=l"(r) : "f"(x), "f"(y)); return r;
}
__device__ __forceinline__ void upk(u64 v, float& x, float& y) {
    asm("mov.b64 {%0,%1},%2;" : "=f"(x), "=f"(y) : "l"(v));
}
__device__ __forceinline__ u64 ffma2(u64 a, u64 b, u64 c) {
    u64 d; asm("fma.rn.f32x2 %0,%1,%2,%3;" : "=l"(d) : "l"(a), "l"(b), "l"(c));
    return d;
}
__device__ __forceinline__ float ex2(float x) {
    float r; asm("ex2.approx.f32 %0,%1;" : "=f"(r) : "f"(x)); return r;
}
__device__ __forceinline__ float rcp(float x) {
    float r; asm("rcp.approx.f32 %0,%1;" : "=f"(r) : "f"(x)); return r;
}
__device__ __forceinline__ float sigmoid_fast(float x) {
    return rcp(1.0f + ex2(-1.4426950408889634f * x));
}
__device__ __forceinline__ float tanh_fast(float x) {
    return 1.0f - 2.0f * rcp(ex2(2.8853900817779268f * x) + 1.0f);
}

__global__ __launch_bounds__(128, 1)
void lstm_rec_kernel(const float* __restrict__ z,
                     const float* __restrict__ Wih,
                     const float* __restrict__ Whh,
                     const float* __restrict__ bih,
                     const float* __restrict__ bhh,
                     float* __restrict__ out)
{
    // W_ih pairs: sWIF[k][lane] = ((Wi[l][2k],Wi[l][2k+1]),(Wf...)), sWGO likewise
    __shared__ ulonglong2 sWIF[NP][32];
    __shared__ ulonglong2 sWGO[NP][32];
    __shared__ u64 sZ[4][4][NP];   // [warp][elem][k] = (z_2k, z_2k+1)
    __shared__ u64 sH[4][4][KP];   // [warp][elem][k] = (h_2k, h_2k+1)

    const int tid = threadIdx.x;

    // ---- one-time staging of W_ih pairs ----
    for (int idx = tid; idx < NP * 32; idx += 128) {
        int k = idx >> 5, l = idx & 31;
        const u64* ri = (const u64*)(Wih + (size_t)l * NL);
        const u64* rf = (const u64*)(Wih + (size_t)(32 + l) * NL);
        const u64* rg = (const u64*)(Wih + (size_t)(64 + l) * NL);
        const u64* ro = (const u64*)(Wih + (size_t)(96 + l) * NL);
        sWIF[k][l] = make_ulonglong2(ri[k], rf[k]);
        sWGO[k][l] = make_ulonglong2(rg[k], ro[k]);
    }
    __syncthreads();

    const int warp = tid >> 5;
    const int lane = tid & 31;
    const int be = blockIdx.x * 16 + warp * 4;

    // ---- W_hh register-resident pairs (rows lane, 32+lane, 64+lane, 96+lane) ----
    u64 wI[KP], wF[KP], wG[KP], wO[KP];
    {
        const u64* ri = (const u64*)(Whh + (size_t)lane * NH);
        const u64* rf = (const u64*)(Whh + (size_t)(32 + lane) * NH);
        const u64* rg = (const u64*)(Whh + (size_t)(64 + lane) * NH);
        const u64* ro = (const u64*)(Whh + (size_t)(96 + lane) * NH);
        #pragma unroll
        for (int k = 0; k < KP; k++) {
            wI[k] = ri[k]; wF[k] = rf[k]; wG[k] = rg[k]; wO[k] = ro[k];
        }
    }

    const u64 bI = pk(bih[lane]       + bhh[lane],        0.f);
    const u64 bF = pk(bih[32 + lane]  + bhh[32 + lane],   0.f);
    const u64 bG = pk(bih[64 + lane]  + bhh[64 + lane],   0.f);
    const u64 bO = pk(bih[96 + lane]  + bhh[96 + lane],   0.f);

    // init h pairs = 0
    if (lane < KP) {
        #pragma unroll
        for (int e = 0; e < 4; e++) sH[warp][e][lane] = 0ull;
    }

    // prefetch z pairs for t=0 (lanes 0..8)
    u64 zp[4];
    if (lane < NP) {
        #pragma unroll
        for (int e = 0; e < 4; e++)
            zp[e] = *(const u64*)(z + ((size_t)(be + e) * NT) * NL + 2 * lane);
    }
    float cS[4] = {0.f, 0.f, 0.f, 0.f};
    float hS[4] = {0.f, 0.f, 0.f, 0.f};
    __syncwarp();

    for (int t = 0; t < NT; t++) {
        if (lane < NP) {
            #pragma unroll
            for (int e = 0; e < 4; e++) sZ[warp][e][lane] = zp[e];
        }
        __syncwarp();   // also orders prev-iter sH writes before reads below
        if (lane < NP && t + 1 < NT) {
            #pragma unroll
            for (int e = 0; e < 4; e++)
                zp[e] = *(const u64*)(z + (((size_t)(be + e) * NT) + t + 1) * NL + 2 * lane);
        }

        u64 aI[4], aF[4], aG[4], aO[4];
        #pragma unroll
        for (int e = 0; e < 4; e++) { aI[e] = bI; aF[e] = bF; aG[e] = bG; aO[e] = bO; }

        // input contribution
        #pragma unroll
        for (int k = 0; k < NP; k++) {
            ulonglong2 wif = sWIF[k][lane];
            ulonglong2 wgo = sWGO[k][lane];
            #pragma unroll
            for (int e = 0; e < 4; e++) {
                u64 zz = sZ[warp][e][k];
                aI[e] = ffma2(zz, wif.x, aI[e]);
                aF[e] = ffma2(zz, wif.y, aF[e]);
                aG[e] = ffma2(zz, wgo.x, aG[e]);
                aO[e] = ffma2(zz, wgo.y, aO[e]);
            }
        }
        // recurrent contribution (weights in registers)
        #pragma unroll
        for (int k = 0; k < KP; k++) {
            #pragma unroll
            for (int e = 0; e < 4; e++) {
                u64 hh = sH[warp][e][k];
                aI[e] = ffma2(hh, wI[k], aI[e]);
                aF[e] = ffma2(hh, wF[k], aF[e]);
                aG[e] = ffma2(hh, wG[k], aG[e]);
                aO[e] = ffma2(hh, wO[k], aO[e]);
            }
        }
        __syncwarp();   // done reading sH before overwrite

        #pragma unroll
        for (int e = 0; e < 4; e++) {
            float x0, x1;
            upk(aI[e], x0, x1); float vi = x0 + x1;
            upk(aF[e], x0, x1); float vf = x0 + x1;
            upk(aG[e], x0, x1); float vg = x0 + x1;
            upk(aO[e], x0, x1); float vo = x0 + x1;
            float i = sigmoid_fast(vi);
            float f = sigmoid_fast(vf);
            float g = tanh_fast(vg);
            float o = sigmoid_fast(vo);
            float c = f * cS[e] + i * g;
            cS[e] = c;
            float h = o * tanh_fast(c);
            hS[e] = h;
            float hn = __shfl_down_sync(0xffffffffu, h, 1);
            if (!(lane & 1)) sH[warp][e][lane >> 1] = pk(h, hn);
            g_hscr[(((size_t)(be + e)) * NT + t) * NH + lane] = h;
        }
        // top-of-loop __syncwarp orders these sH writes before next reads
    }

    // out layout: [z_pred (B*T*18) | h_n (B*32) | c_n (B*32)]
    float* hOut = out + (size_t)NB * NT * NL;
    float* cOut = hOut + (size_t)NB * NH;
    #pragma unroll
    for (int e = 0; e < 4; e++) {
        hOut[(be + e) * NH + lane] = hS[e];
        cOut[(be + e) * NH + lane] = cS[e];
    }
}

// ---- kernel 2: z_pred = h @ Wout^T + bout, tile of 64 rows per block ----
__global__ __launch_bounds__(256)
void proj_kernel(const float* __restrict__ Wout,
                 const float* __restrict__ bout,
                 float* __restrict__ out)
{
    __shared__ u64   sW[NL][KP];        // Wout pairs
    __shared__ float sB[NL];
    __shared__ u64   sHp[64][KP + 1];   // h pairs, padded
    __shared__ float sO[64 * NL];

    const int tid = threadIdx.x;
    const size_t base = (size_t)blockIdx.x * 64;

    for (int idx = tid; idx < NL * KP; idx += 256) {
        int m = idx >> 4, k = idx & 15;
        sW[m][k] = ((const u64*)(Wout + (size_t)m * NH))[k];
    }
    if (tid < NL) sB[tid] = bout[tid];

    // load 64x32 h tile (1024 u64, coalesced)
    const u64* hsrc = (const u64*)(g_hscr + base * NH);
    #pragma unroll
    for (int s = 0; s < 4; s++) {
        int idx = tid + s * 256;
        sHp[idx >> 4][idx & 15] = hsrc[idx];
    }
    __syncthreads();

    const int row = tid >> 2;
    const int q = tid & 3;
    u64 hp[KP];
    #pragma unroll
    for (int k = 0; k < KP; k++) hp[k] = sHp[row][k];

    #pragma unroll
    for (int s = 0; s < 5; s++) {
        int m = q + 4 * s;
        if (m < NL) {
            u64 acc = pk(sB[m], 0.f);
            #pragma unroll
            for (int k = 0; k < KP; k++) acc = ffma2(hp[k], sW[m][k], acc);
            float lo, hi; upk(acc, lo, hi);
            sO[row * NL + m] = lo + hi;
        }
    }
    __syncthreads();

    float* dst = out + base * NL;
    #pragma unroll
    for (int i = tid; i < 64 * NL; i += 256) dst[i] = sO[i];
}

extern "C" void kernel_launch(void* const* d_in, const int* in_sizes, int n_in,
                              void* d_out, int out_size)
{
    const float* z    = (const float*)d_in[0];
    const float* Wih  = (const float*)d_in[1];
    const float* Whh  = (const float*)d_in[2];
    const float* bih  = (const float*)d_in[3];
    const float* bhh  = (const float*)d_in[4];
    const float* Wout = (const float*)d_in[5];
    const float* bout = (const float*)d_in[6];
    float* out = (float*)d_out;

    lstm_rec_kernel<<<NB / 16, 128>>>(z, Wih, Whh, bih, bhh, out);
    proj_kernel<<<(NB * NT) / 64, 256>>>(Wout, bout, out);
}

// round 6
// speedup vs baseline: 1.4071x; 1.4071x over previous
#include <cuda_runtime.h>

// LSTM B=2048, T=512, LATENT=18, HID=32 (gates i,f,g,o).
// Kernel 1 (serial recurrence): 128 blocks x 256 threads (8 warps/SM, 2
//   warps/SMSP). Warp handles 2 batch elems; lane = hidden index. BOTH W_ih
//   and W_hh register-resident as f32x2 pairs (~245 regs/thread, fits the
//   256-reg cap at 1 block/SM). Pair accumulation: acc holds (even,odd)
//   partials; multiplier (v_2k,v_2k+1) is one broadcast LDS.64; horizontal
//   add at the end. h -> global scratch for kernel 2.
// Kernel 2 (streaming): z_pred = h @ W_out^T + b_out, thread-per-row.
// R5/R6: proj sW staging is a strided loop over all 288 entries (R4 bug:
// single predicated store with tid<288 on 256 threads -> rows 16,17 garbage).

#define NB 2048
#define NT 512
#define NL 18
#define NH 32
#define NP 9     // latent pairs
#define KP 16    // hidden pairs

typedef unsigned long long u64;

__device__ float g_hscr[(size_t)NB * NT * NH];   // 134 MB scratch h[B][T][32]

__device__ __forceinline__ u64 pk(float x, float y) {
    u64 r; asm("mov.b64 %0,{%1,%2};" : "=l"(r) : "f"(x), "f"(y)); return r;
}
__device__ __forceinline__ void upk(u64 v, float& x, float& y) {
    asm("mov.b64 {%0,%1},%2;" : "=f"(x), "=f"(y) : "l"(v));
}
__device__ __forceinline__ u64 ffma2(u64 a, u64 b, u64 c) {
    u64 d; asm("fma.rn.f32x2 %0,%1,%2,%3;" : "=l"(d) : "l"(a), "l"(b), "l"(c));
    return d;
}
__device__ __forceinline__ float ex2(float x) {
    float r; asm("ex2.approx.f32 %0,%1;" : "=f"(r) : "f"(x)); return r;
}
__device__ __forceinline__ float rcp(float x) {
    float r; asm("rcp.approx.f32 %0,%1;" : "=f"(r) : "f"(x)); return r;
}
__device__ __forceinline__ float sigmoid_fast(float x) {
    return rcp(1.0f + ex2(-1.4426950408889634f * x));
}
__device__ __forceinline__ float tanh_fast(float x) {
    return 1.0f - 2.0f * rcp(ex2(2.8853900817779268f * x) + 1.0f);
}

__global__ __launch_bounds__(256, 1)
void lstm_rec_kernel(const float* __restrict__ z,
                     const float* __restrict__ Wih,
                     const float* __restrict__ Whh,
                     const float* __restrict__ bih,
                     const float* __restrict__ bhh,
                     float* __restrict__ out)
{
    __shared__ u64 sZ[8][2][NP];   // [warp][elem][k] = (z_2k, z_2k+1)
    __shared__ u64 sH[8][2][KP];   // [warp][elem][k] = (h_2k, h_2k+1)

    const int tid  = threadIdx.x;
    const int warp = tid >> 5;
    const int lane = tid & 31;
    const int be   = blockIdx.x * 16 + warp * 2;

    // ---- register-resident weights (gate rows lane, 32+lane, 64+lane, 96+lane)
    u64 vI[NP], vF[NP], vG[NP], vO[NP];      // W_ih pairs
    u64 wI[KP], wF[KP], wG[KP], wO[KP];      // W_hh pairs
    {
        const u64* ri = (const u64*)(Wih + (size_t)lane * NL);
        const u64* rf = (const u64*)(Wih + (size_t)(32 + lane) * NL);
        const u64* rg = (const u64*)(Wih + (size_t)(64 + lane) * NL);
        const u64* ro = (const u64*)(Wih + (size_t)(96 + lane) * NL);
        #pragma unroll
        for (int k = 0; k < NP; k++) {
            vI[k] = ri[k]; vF[k] = rf[k]; vG[k] = rg[k]; vO[k] = ro[k];
        }
    }
    {
        const u64* ri = (const u64*)(Whh + (size_t)lane * NH);
        const u64* rf = (const u64*)(Whh + (size_t)(32 + lane) * NH);
        const u64* rg = (const u64*)(Whh + (size_t)(64 + lane) * NH);
        const u64* ro = (const u64*)(Whh + (size_t)(96 + lane) * NH);
        #pragma unroll
        for (int k = 0; k < KP; k++) {
            wI[k] = ri[k]; wF[k] = rf[k]; wG[k] = rg[k]; wO[k] = ro[k];
        }
    }

    const u64 bI = pk(bih[lane]      + bhh[lane],      0.f);
    const u64 bF = pk(bih[32 + lane] + bhh[32 + lane], 0.f);
    const u64 bG = pk(bih[64 + lane] + bhh[64 + lane], 0.f);
    const u64 bO = pk(bih[96 + lane] + bhh[96 + lane], 0.f);

    if (lane < KP) {
        sH[warp][0][lane] = 0ull;
        sH[warp][1][lane] = 0ull;
    }

    // z base for this warp's two elements, offset by pair lane (lanes 0..8)
    const float* zb0 = z + ((size_t)be       * NT) * NL + 2 * lane;
    const float* zb1 = z + ((size_t)(be + 1) * NT) * NL + 2 * lane;
    u64 zp0 = 0, zp1 = 0;
    if (lane < NP) {
        zp0 = *(const u64*)zb0;
        zp1 = *(const u64*)zb1;
    }
    float c0 = 0.f, c1 = 0.f, h0 = 0.f, h1 = 0.f;

    float* hs0 = g_hscr + ((size_t)be       * NT) * NH + lane;
    float* hs1 = g_hscr + ((size_t)(be + 1) * NT) * NH + lane;
    __syncwarp();

    for (int t = 0; t < NT; t++) {
        if (lane < NP) {
            sZ[warp][0][lane] = zp0;
            sZ[warp][1][lane] = zp1;
        }
        __syncwarp();   // orders z stage + prev sH writes before reads below
        if (lane < NP && t + 1 < NT) {
            zp0 = *(const u64*)(zb0 + (t + 1) * NL);
            zp1 = *(const u64*)(zb1 + (t + 1) * NL);
        }

        u64 aI0 = bI, aF0 = bF, aG0 = bG, aO0 = bO;
        u64 aI1 = bI, aF1 = bF, aG1 = bG, aO1 = bO;

        #pragma unroll
        for (int k = 0; k < NP; k++) {
            u64 z0 = sZ[warp][0][k];
            u64 z1 = sZ[warp][1][k];
            aI0 = ffma2(z0, vI[k], aI0);  aI1 = ffma2(z1, vI[k], aI1);
            aF0 = ffma2(z0, vF[k], aF0);  aF1 = ffma2(z1, vF[k], aF1);
            aG0 = ffma2(z0, vG[k], aG0);  aG1 = ffma2(z1, vG[k], aG1);
            aO0 = ffma2(z0, vO[k], aO0);  aO1 = ffma2(z1, vO[k], aO1);
        }
        #pragma unroll
        for (int k = 0; k < KP; k++) {
            u64 p0 = sH[warp][0][k];
            u64 p1 = sH[warp][1][k];
            aI0 = ffma2(p0, wI[k], aI0);  aI1 = ffma2(p1, wI[k], aI1);
            aF0 = ffma2(p0, wF[k], aF0);  aF1 = ffma2(p1, wF[k], aF1);
            aG0 = ffma2(p0, wG[k], aG0);  aG1 = ffma2(p1, wG[k], aG1);
            aO0 = ffma2(p0, wO[k], aO0);  aO1 = ffma2(p1, wO[k], aO1);
        }
        __syncwarp();   // done reading sH before overwrite

        float x, y, vi, vf, vg, vo, i, f, g, o;
        // elem 0
        upk(aI0, x, y); vi = x + y;
        upk(aF0, x, y); vf = x + y;
        upk(aG0, x, y); vg = x + y;
        upk(aO0, x, y); vo = x + y;
        i = sigmoid_fast(vi); f = sigmoid_fast(vf);
        g = tanh_fast(vg);    o = sigmoid_fast(vo);
        c0 = f * c0 + i * g;
        h0 = o * tanh_fast(c0);
        // elem 1
        upk(aI1, x, y); vi = x + y;
        upk(aF1, x, y); vf = x + y;
        upk(aG1, x, y); vg = x + y;
        upk(aO1, x, y); vo = x + y;
        i = sigmoid_fast(vi); f = sigmoid_fast(vf);
        g = tanh_fast(vg);    o = sigmoid_fast(vo);
        c1 = f * c1 + i * g;
        h1 = o * tanh_fast(c1);

        float hn0 = __shfl_down_sync(0xffffffffu, h0, 1);
        float hn1 = __shfl_down_sync(0xffffffffu, h1, 1);
        if (!(lane & 1)) {
            sH[warp][0][lane >> 1] = pk(h0, hn0);
            sH[warp][1][lane >> 1] = pk(h1, hn1);
        }
        hs0[(size_t)t * NH] = h0;
        hs1[(size_t)t * NH] = h1;
        // top-of-loop __syncwarp orders sH writes before next reads
    }

    // out layout: [z_pred (B*T*18) | h_n (B*32) | c_n (B*32)]
    float* hOut = out + (size_t)NB * NT * NL;
    float* cOut = hOut + (size_t)NB * NH;
    hOut[(size_t)be * NH + lane]       = h0;
    hOut[(size_t)(be + 1) * NH + lane] = h1;
    cOut[(size_t)be * NH + lane]       = c0;
    cOut[(size_t)(be + 1) * NH + lane] = c1;
}

// ---- kernel 2: z_pred = h @ Wout^T + bout. Thread-per-row streaming. ----
#define PROWS 256
__global__ __launch_bounds__(PROWS)
void proj_kernel(const float* __restrict__ Wout,
                 const float* __restrict__ bout,
                 float* __restrict__ out)
{
    __shared__ u64   sW[NL][KP];       // Wout row m as pairs
    __shared__ float sB[NL];
    __shared__ float sO[PROWS * NL];

    const int tid = threadIdx.x;
    const size_t base = (size_t)blockIdx.x * PROWS;

    // NL*KP = 288 entries > 256 threads: MUST be a strided loop.
    for (int idx = tid; idx < NL * KP; idx += PROWS) {
        int m = idx / KP, k = idx % KP;
        sW[m][k] = ((const u64*)(Wout + (size_t)m * NH))[k];
    }
    if (tid < NL) sB[tid] = bout[tid];
    __syncthreads();

    // each thread: one (b,t) row; its 32 floats = one 128B line (L1-friendly)
    const u64* hr = (const u64*)(g_hscr + (base + tid) * NH);
    u64 h[KP];
    #pragma unroll
    for (int k = 0; k < KP; k++) h[k] = hr[k];

    #pragma unroll
    for (int m = 0; m < NL; m++) {
        u64 acc = pk(sB[m], 0.f);
        #pragma unroll
        for (int k = 0; k < KP; k++) acc = ffma2(h[k], sW[m][k], acc);
        float lo, hi; upk(acc, lo, hi);
        sO[tid * NL + m] = lo + hi;
    }
    __syncthreads();

    float* dst = out + base * NL;
    #pragma unroll
    for (int i = 0; i < NL; i++) dst[tid + i * PROWS] = sO[tid + i * PROWS];
}

extern "C" void kernel_launch(void* const* d_in, const int* in_sizes, int n_in,
                              void* d_out, int out_size)
{
    const float* z    = (const float*)d_in[0];
    const float* Wih  = (const float*)d_in[1];
    const float* Whh  = (const float*)d_in[2];
    const float* bih  = (const float*)d_in[3];
    const float* bhh  = (const float*)d_in[4];
    const float* Wout = (const float*)d_in[5];
    const float* bout = (const float*)d_in[6];
    float* out = (float*)d_out;

    lstm_rec_kernel<<<NB / 16, 256>>>(z, Wih, Whh, bih, bhh, out);
    proj_kernel<<<(NB * NT) / PROWS, PROWS>>>(Wout, bout, out);
}